// round 14
// baseline (speedup 1.0000x reference)
#include <cuda_runtime.h>
#include <cuda_fp16.h>
#include <math.h>

#define BB     8192
#define MM     200
#define EE     64
#define NOTHER 128
#define H1     96
#define F1     128
#define F2     85
#define F3     64

__device__ float g_tmp[BB * EE];

// ---------------- Kernel 1: attention + weighted sum (5 CTAs/SM) ----------------
// smem u32: W2 3328, hist 200*36=7200; floats: tgt 64, c 96, w2 96, aij 208, part 512
#define SM1_U32  (3328 + 7200 + 64 + 96 + 96 + 208 + 512)
#define SM1_BYTES (SM1_U32 * 4)

__global__ __launch_bounds__(256, 5)
void din_attn(const float* __restrict__ hist, const float* __restrict__ target,
              const float* __restrict__ aW1, const float* __restrict__ ab1,
              const float* __restrict__ aW2, const float* __restrict__ ab2)
{
    extern __shared__ unsigned sm1[];
    unsigned* s_W2 = sm1;                 // half2 W1eff [k2*104 + n]
    unsigned* s_h  = sm1 + 3328;          // half2 hist  [row*36 + k2], 200 rows
    float* s_tgt  = (float*)(sm1 + 3328 + 7200);
    float* s_c    = s_tgt + 64;
    float* s_w2   = s_c + 96;
    float* s_aij  = s_w2 + 96;
    float* s_part = s_aij + 208;          // [8][64]

    const int b = blockIdx.x;
    const int t = threadIdx.x;
    const float* hb = hist + (size_t)b * MM * EE;

    if (t < EE) s_tgt[t] = target[(size_t)b * EE + t];
    if (t < H1) s_w2[t]  = aW2[t];
    __syncthreads();

    // stage hist -> smem fp16 (200 rows; no pad rows — MMA rows are independent,
    // tile-12 reads beyond row 199 hit in-bounds smem garbage whose outputs are discarded)
    for (int idx = t; idx < MM * 16; idx += 256) {
        const int row = idx >> 4, q = idx & 15;
        float4 v = ((const float4*)(hb + (size_t)row * EE))[q];
        __half2 h01 = __floats2half2_rn(v.x, v.y);
        __half2 h23 = __floats2half2_rn(v.z, v.w);
        uint2 st;
        st.x = *(unsigned*)&h01;
        st.y = *(unsigned*)&h23;
        *(uint2*)(s_h + row * 36 + 2 * q) = st;
    }

    for (int idx = t; idx < 32 * H1; idx += 256) {
        const int k2 = idx / H1, n = idx - k2 * H1;
        const int e0 = 2 * k2, e1 = 2 * k2 + 1;
        float v0 = aW1[e0 * H1 + n] + s_tgt[e0] * aW1[(EE + e0) * H1 + n];
        float v1 = aW1[e1 * H1 + n] + s_tgt[e1] * aW1[(EE + e1) * H1 + n];
        __half2 p = __floats2half2_rn(v0, v1);
        s_W2[k2 * 104 + n] = *(unsigned*)&p;
    }
    if (t < H1) {
        float acc = ab1[t];
        #pragma unroll 8
        for (int e = 0; e < EE; e++)
            acc = fmaf(s_tgt[e], aW1[(2 * EE + e) * H1 + t], acc);
        s_c[t] = acc;
    }
    __syncthreads();

    const int warp = t >> 5, lane = t & 31;
    const int gid = lane >> 2, tig = lane & 3;
    const float bias2 = ab2[0];

    // ---- Phase 1: fp16 mma m16n8k16, one m-tile per warp, round-robin ----
    for (int mt = warp; mt < 13; mt += 8) {
        unsigned A[4][4];
        const unsigned* hp = s_h + (mt * 16 + gid) * 36 + tig;
        #pragma unroll
        for (int ks = 0; ks < 4; ks++) {
            A[ks][0] = hp[8 * ks];
            A[ks][1] = hp[288 + 8 * ks];
            A[ks][2] = hp[8 * ks + 4];
            A[ks][3] = hp[288 + 8 * ks + 4];
        }

        float aij0 = 0.f, aij1 = 0.f;
        const unsigned* wb = s_W2 + tig * 104 + gid;

        #pragma unroll 1
        for (int nt = 0; nt < 12; nt++) {
            float c0 = 0.f, c1 = 0.f, c2 = 0.f, c3 = 0.f;
            #pragma unroll
            for (int ks = 0; ks < 4; ks++) {
                const unsigned b0 = wb[ks * 832 + nt * 8];
                const unsigned b1 = wb[ks * 832 + 416 + nt * 8];
                asm volatile(
                    "mma.sync.aligned.m16n8k16.row.col.f32.f16.f16.f32 "
                    "{%0,%1,%2,%3}, {%4,%5,%6,%7}, {%8,%9}, {%0,%1,%2,%3};"
                    : "+f"(c0), "+f"(c1), "+f"(c2), "+f"(c3)
                    : "r"(A[ks][0]), "r"(A[ks][1]), "r"(A[ks][2]), "r"(A[ks][3]),
                      "r"(b0), "r"(b1));
            }
            const int j0 = nt * 8 + 2 * tig;
            const float cc0 = s_c[j0],  cc1 = s_c[j0 + 1];
            const float w0  = s_w2[j0], w1  = s_w2[j0 + 1];
            aij0 = fmaf(fmaxf(c0 + cc0, 0.f), w0, aij0);
            aij0 = fmaf(fmaxf(c1 + cc1, 0.f), w1, aij0);
            aij1 = fmaf(fmaxf(c2 + cc0, 0.f), w0, aij1);
            aij1 = fmaf(fmaxf(c3 + cc1, 0.f), w1, aij1);
        }
        aij0 += __shfl_xor_sync(0xffffffffu, aij0, 1);
        aij0 += __shfl_xor_sync(0xffffffffu, aij0, 2);
        aij1 += __shfl_xor_sync(0xffffffffu, aij1, 1);
        aij1 += __shfl_xor_sync(0xffffffffu, aij1, 2);
        if (tig == 0) {
            const int r0 = mt * 16 + gid;
            if (r0 < MM)     s_aij[r0]     = aij0 + bias2;
            if (r0 + 8 < MM) s_aij[r0 + 8] = aij1 + bias2;
        }
    }
    __syncthreads();

    // ---- Phase 2: tmp[e] = sum_m aij[m]*hist[m][e] (fp16 smem, conflict-free) ----
    {
        const int e2 = lane;
        const int m0 = warp * 25;
        float acc0 = 0.f, acc1 = 0.f;
        #pragma unroll 5
        for (int m = m0; m < m0 + 25; m++) {
            const unsigned u = s_h[m * 36 + e2];
            const __half2 h = *(const __half2*)&u;
            const float2 f = __half22float2(h);
            const float a = s_aij[m];
            acc0 = fmaf(a, f.x, acc0);
            acc1 = fmaf(a, f.y, acc1);
        }
        float2 st; st.x = acc0; st.y = acc1;
        *(float2*)(s_part + warp * 64 + 2 * e2) = st;
    }
    __syncthreads();
    if (t < EE) {
        float v = 0.f;
        #pragma unroll
        for (int c = 0; c < 8; c++)
            v += s_part[c * 64 + t];
        g_tmp[(size_t)b * EE + t] = v;
    }
}

// ---------------- Kernel 2: MLP v5 (R12, unchanged) ----------------
#define NB   16
#define MX   (NB * 256)
#define MH1  (NB * F1)
#define MH2  (NB * 88)
#define SM2_BYTES ((MX + MH1 + MH2) * 4)

__global__ __launch_bounds__(512)
void din_mlp(const float* __restrict__ target, const float* __restrict__ other,
             const float* __restrict__ oW1, const float* __restrict__ ob1,
             const float* __restrict__ oW2, const float* __restrict__ ob2,
             const float* __restrict__ oW3, const float* __restrict__ ob3,
             const float* __restrict__ fW,  const float* __restrict__ fb,
             float* __restrict__ out)
{
    extern __shared__ float sm2[];
    float* s_x  = sm2;
    float* s_h1 = sm2 + MX;
    float* s_h2 = sm2 + MX + MH1;

    const int t = threadIdx.x;
    const int B0 = blockIdx.x * NB;

    for (int idx = t; idx < NB * 16; idx += 512) {
        const int bi = idx >> 4, q = idx & 15;
        float4 v = ((const float4*)(g_tmp + (size_t)(B0 + bi) * EE))[q];
        *(float4*)(s_x + bi * 256 + 4 * q) = v;
        float4 u = ((const float4*)(target + (size_t)(B0 + bi) * EE))[q];
        *(float4*)(s_x + bi * 256 + 64 + 4 * q) = u;
    }
    for (int idx = t; idx < NB * 32; idx += 512) {
        const int bi = idx >> 5, q = idx & 31;
        float4 v = ((const float4*)(other + (size_t)(B0 + bi) * NOTHER))[q];
        *(float4*)(s_x + bi * 256 + 128 + 4 * q) = v;
    }
    __syncthreads();

    const int warp = t >> 5, lane = t & 31;
    const float* x0 = s_x + warp * 256;

    {
        const int j0 = lane * 4;
        float4 bv = *(const float4*)(ob1 + j0);
        float ax = bv.x, ay = bv.y, az = bv.z, aw = bv.w;
        #pragma unroll 4
        for (int k = 0; k < 256; k += 4) {
            const float4 v0 = *(const float4*)(x0 + k);
            #pragma unroll
            for (int i = 0; i < 4; i++) {
                const float4 w = *(const float4*)(oW1 + (k + i) * F1 + j0);
                const float e0 = (i == 0) ? v0.x : (i == 1) ? v0.y : (i == 2) ? v0.z : v0.w;
                ax = fmaf(e0, w.x, ax); ay = fmaf(e0, w.y, ay);
                az = fmaf(e0, w.z, az); aw = fmaf(e0, w.w, aw);
            }
        }
        float4 r;
        r.x = fmaxf(ax, 0.f); r.y = fmaxf(ay, 0.f);
        r.z = fmaxf(az, 0.f); r.w = fmaxf(aw, 0.f);
        *(float4*)(s_h1 + warp * F1 + j0) = r;
    }
    __syncwarp();

    const float* h10 = s_h1 + warp * F1;

    {
        const int j2 = lane + 64;
        const bool g2 = (j2 < F2);
        float a0 = ob2[lane], a1 = ob2[lane + 32], a2 = g2 ? ob2[j2] : 0.f;
        #pragma unroll 4
        for (int k = 0; k < F1; k += 4) {
            const float4 v0 = *(const float4*)(h10 + k);
            #pragma unroll
            for (int i = 0; i < 4; i++) {
                const float* wr = oW2 + (k + i) * F2;
                const float e0 = (i == 0) ? v0.x : (i == 1) ? v0.y : (i == 2) ? v0.z : v0.w;
                a0 = fmaf(e0, wr[lane], a0);
                a1 = fmaf(e0, wr[lane + 32], a1);
                if (g2) a2 = fmaf(e0, wr[j2], a2);
            }
        }
        s_h2[warp * 88 + lane]      = fmaxf(a0, 0.f);
        s_h2[warp * 88 + lane + 32] = fmaxf(a1, 0.f);
        if (g2) s_h2[warp * 88 + j2] = fmaxf(a2, 0.f);
    }
    __syncwarp();

    {
        float a0 = ob3[lane], a1 = ob3[lane + 32];
        const float* h20 = s_h2 + warp * 88;
        #pragma unroll 5
        for (int k = 0; k < F2; k++) {
            const float v0 = h20[k];
            a0 = fmaf(v0, oW3[k * F3 + lane], a0);
            a1 = fmaf(v0, oW3[k * F3 + lane + 32], a1);
        }
        float v = fmaxf(a0, 0.f) * fW[lane] + fmaxf(a1, 0.f) * fW[lane + 32];
        #pragma unroll
        for (int off = 16; off; off >>= 1)
            v += __shfl_xor_sync(0xffffffffu, v, off);
        if (lane == 0)
            out[B0 + warp] = 1.f / (1.f + expf(-(v + fb[0])));
    }
}

extern "C" void kernel_launch(void* const* d_in, const int* in_sizes, int n_in,
                              void* d_out, int out_size)
{
    const float* hist   = (const float*)d_in[0];
    const float* target = (const float*)d_in[1];
    const float* other  = (const float*)d_in[2];
    const float* aW1    = (const float*)d_in[3];
    const float* ab1    = (const float*)d_in[4];
    const float* aW2    = (const float*)d_in[5];
    const float* ab2    = (const float*)d_in[6];
    const float* oW1    = (const float*)d_in[7];
    const float* ob1    = (const float*)d_in[8];
    const float* oW2    = (const float*)d_in[9];
    const float* ob2    = (const float*)d_in[10];
    const float* oW3    = (const float*)d_in[11];
    const float* ob3    = (const float*)d_in[12];
    const float* fW     = (const float*)d_in[13];
    const float* fb     = (const float*)d_in[14];
    float* out = (float*)d_out;

    static int configured = 0;
    if (!configured) {
        cudaFuncSetAttribute(din_attn, cudaFuncAttributeMaxDynamicSharedMemorySize,
                             SM1_BYTES);
        cudaFuncSetAttribute(din_mlp, cudaFuncAttributeMaxDynamicSharedMemorySize,
                             SM2_BYTES);
        configured = 1;
    }
    din_attn<<<BB, 256, SM1_BYTES>>>(hist, target, aW1, ab1, aW2, ab2);
    din_mlp<<<BB / NB, 512, SM2_BYTES>>>(target, other, oW1, ob1, oW2, ob2,
                                         oW3, ob3, fW, fb, out);
}

// round 15
// speedup vs baseline: 1.1387x; 1.1387x over previous
#include <cuda_runtime.h>
#include <cuda_fp16.h>
#include <math.h>

#define BB     8192
#define MM     200
#define EE     64
#define NOTHER 128
#define H1     96
#define F1     128
#define F2     85
#define F3     64

__device__ float g_tmp[BB * EE];
__device__ unsigned g_w1t[16 * 32 * 32 * 2];   // oW1 as tf32 bits, fragment-ordered

__device__ __forceinline__ unsigned f2tf32(float f) {
    unsigned r;
    asm("cvt.rna.tf32.f32 %0, %1;" : "=r"(r) : "f"(f));
    return r;
}

// ---------------- Kernel 0: one-time oW1 -> tf32 fragment layout ----------------
// idx = ((nt*32 + ks)*32 + lane)*2 + r ; value = tf32(oW1[(8ks+tig+4r)*128 + 8nt+gid])
__global__ __launch_bounds__(256)
void cvt_w1(const float* __restrict__ oW1)
{
    const int idx = blockIdx.x * 256 + threadIdx.x;       // 32768 total
    const int r    = idx & 1;
    const int lane = (idx >> 1) & 31;
    const int ks   = (idx >> 6) & 31;
    const int nt   = idx >> 11;
    const int tig = lane & 3, gid = lane >> 2;
    const int k = 8 * ks + tig + 4 * r;
    const int n = 8 * nt + gid;
    g_w1t[idx] = f2tf32(oW1[k * F1 + n]);
}

// ---------------- Kernel 1: attention + weighted sum (R13 exact) ----------------
#define SM1_U32  (3328 + 7488 + 64 + 96 + 96 + 208 + 512)
#define SM1_BYTES (SM1_U32 * 4)

__global__ __launch_bounds__(256, 4)
void din_attn(const float* __restrict__ hist, const float* __restrict__ target,
              const float* __restrict__ aW1, const float* __restrict__ ab1,
              const float* __restrict__ aW2, const float* __restrict__ ab2)
{
    extern __shared__ unsigned sm1[];
    unsigned* s_W2 = sm1;
    unsigned* s_h  = sm1 + 3328;
    float* s_tgt  = (float*)(sm1 + 3328 + 7488);
    float* s_c    = s_tgt + 64;
    float* s_w2   = s_c + 96;
    float* s_aij  = s_w2 + 96;
    float* s_part = s_aij + 208;

    const int b = blockIdx.x;
    const int t = threadIdx.x;
    const float* hb = hist + (size_t)b * MM * EE;

    if (t < EE) s_tgt[t] = target[(size_t)b * EE + t];
    if (t < H1) s_w2[t]  = aW2[t];
    __syncthreads();

    for (int idx = t; idx < MM * 16; idx += 256) {
        const int row = idx >> 4, q = idx & 15;
        float4 v = ((const float4*)(hb + (size_t)row * EE))[q];
        __half2 h01 = __floats2half2_rn(v.x, v.y);
        __half2 h23 = __floats2half2_rn(v.z, v.w);
        uint2 st;
        st.x = *(unsigned*)&h01;
        st.y = *(unsigned*)&h23;
        *(uint2*)(s_h + row * 36 + 2 * q) = st;
    }
    for (int idx = t; idx < 8 * 36; idx += 256)
        s_h[200 * 36 + idx] = 0u;

    for (int idx = t; idx < 32 * H1; idx += 256) {
        const int k2 = idx / H1, n = idx - k2 * H1;
        const int e0 = 2 * k2, e1 = 2 * k2 + 1;
        float v0 = aW1[e0 * H1 + n] + s_tgt[e0] * aW1[(EE + e0) * H1 + n];
        float v1 = aW1[e1 * H1 + n] + s_tgt[e1] * aW1[(EE + e1) * H1 + n];
        __half2 p = __floats2half2_rn(v0, v1);
        s_W2[k2 * 104 + n] = *(unsigned*)&p;
    }
    if (t < H1) {
        float acc = ab1[t];
        #pragma unroll 8
        for (int e = 0; e < EE; e++)
            acc = fmaf(s_tgt[e], aW1[(2 * EE + e) * H1 + t], acc);
        s_c[t] = acc;
    }
    __syncthreads();

    const int warp = t >> 5, lane = t & 31;
    const int gid = lane >> 2, tig = lane & 3;
    const float bias2 = ab2[0];

    {
        const int mt0 = warp;
        const int mt1 = warp + 8;
        const bool two = (mt1 < 13);

        unsigned A0[4][4], A1[4][4];
        {
            const unsigned* hp0 = s_h + (mt0 * 16 + gid) * 36 + tig;
            #pragma unroll
            for (int ks = 0; ks < 4; ks++) {
                A0[ks][0] = hp0[8 * ks];
                A0[ks][1] = hp0[288 + 8 * ks];
                A0[ks][2] = hp0[8 * ks + 4];
                A0[ks][3] = hp0[288 + 8 * ks + 4];
            }
            if (two) {
                const unsigned* hp1 = s_h + (mt1 * 16 + gid) * 36 + tig;
                #pragma unroll
                for (int ks = 0; ks < 4; ks++) {
                    A1[ks][0] = hp1[8 * ks];
                    A1[ks][1] = hp1[288 + 8 * ks];
                    A1[ks][2] = hp1[8 * ks + 4];
                    A1[ks][3] = hp1[288 + 8 * ks + 4];
                }
            }
        }

        float aij0 = 0.f, aij1 = 0.f, aij2 = 0.f, aij3 = 0.f;
        const unsigned* wb = s_W2 + tig * 104 + gid;

        #pragma unroll 1
        for (int nt = 0; nt < 12; nt++) {
            float c0 = 0.f, c1 = 0.f, c2 = 0.f, c3 = 0.f;
            float d0 = 0.f, d1 = 0.f, d2 = 0.f, d3 = 0.f;
            #pragma unroll
            for (int ks = 0; ks < 4; ks++) {
                const unsigned b0 = wb[ks * 832 + nt * 8];
                const unsigned b1 = wb[ks * 832 + 416 + nt * 8];
                asm volatile(
                    "mma.sync.aligned.m16n8k16.row.col.f32.f16.f16.f32 "
                    "{%0,%1,%2,%3}, {%4,%5,%6,%7}, {%8,%9}, {%0,%1,%2,%3};"
                    : "+f"(c0), "+f"(c1), "+f"(c2), "+f"(c3)
                    : "r"(A0[ks][0]), "r"(A0[ks][1]), "r"(A0[ks][2]), "r"(A0[ks][3]),
                      "r"(b0), "r"(b1));
                if (two)
                    asm volatile(
                        "mma.sync.aligned.m16n8k16.row.col.f32.f16.f16.f32 "
                        "{%0,%1,%2,%3}, {%4,%5,%6,%7}, {%8,%9}, {%0,%1,%2,%3};"
                        : "+f"(d0), "+f"(d1), "+f"(d2), "+f"(d3)
                        : "r"(A1[ks][0]), "r"(A1[ks][1]), "r"(A1[ks][2]), "r"(A1[ks][3]),
                          "r"(b0), "r"(b1));
            }
            const int j0 = nt * 8 + 2 * tig;
            const float cc0 = s_c[j0],  cc1 = s_c[j0 + 1];
            const float w0  = s_w2[j0], w1  = s_w2[j0 + 1];
            aij0 = fmaf(fmaxf(c0 + cc0, 0.f), w0, aij0);
            aij0 = fmaf(fmaxf(c1 + cc1, 0.f), w1, aij0);
            aij1 = fmaf(fmaxf(c2 + cc0, 0.f), w0, aij1);
            aij1 = fmaf(fmaxf(c3 + cc1, 0.f), w1, aij1);
            if (two) {
                aij2 = fmaf(fmaxf(d0 + cc0, 0.f), w0, aij2);
                aij2 = fmaf(fmaxf(d1 + cc1, 0.f), w1, aij2);
                aij3 = fmaf(fmaxf(d2 + cc0, 0.f), w0, aij3);
                aij3 = fmaf(fmaxf(d3 + cc1, 0.f), w1, aij3);
            }
        }
        aij0 += __shfl_xor_sync(0xffffffffu, aij0, 1);
        aij0 += __shfl_xor_sync(0xffffffffu, aij0, 2);
        aij1 += __shfl_xor_sync(0xffffffffu, aij1, 1);
        aij1 += __shfl_xor_sync(0xffffffffu, aij1, 2);
        aij2 += __shfl_xor_sync(0xffffffffu, aij2, 1);
        aij2 += __shfl_xor_sync(0xffffffffu, aij2, 2);
        aij3 += __shfl_xor_sync(0xffffffffu, aij3, 1);
        aij3 += __shfl_xor_sync(0xffffffffu, aij3, 2);
        if (tig == 0) {
            const int r0 = mt0 * 16 + gid;
            s_aij[r0] = aij0 + bias2;
            if (r0 + 8 < MM) s_aij[r0 + 8] = aij1 + bias2;
            if (two) {
                const int r2 = mt1 * 16 + gid;
                if (r2 < MM)     s_aij[r2]     = aij2 + bias2;
                if (r2 + 8 < MM) s_aij[r2 + 8] = aij3 + bias2;
            }
        }
    }
    __syncthreads();

    {
        const int e2 = lane;
        const int m0 = warp * 25;
        float acc0 = 0.f, acc1 = 0.f;
        #pragma unroll 5
        for (int m = m0; m < m0 + 25; m++) {
            const unsigned u = s_h[m * 36 + e2];
            const __half2 h = *(const __half2*)&u;
            const float2 f = __half22float2(h);
            const float a = s_aij[m];
            acc0 = fmaf(a, f.x, acc0);
            acc1 = fmaf(a, f.y, acc1);
        }
        float2 st; st.x = acc0; st.y = acc1;
        *(float2*)(s_part + warp * 64 + 2 * e2) = st;
    }
    __syncthreads();
    if (t < EE) {
        float v = 0.f;
        #pragma unroll
        for (int c = 0; c < 8; c++)
            v += s_part[c * 64 + t];
        g_tmp[(size_t)b * EE + t] = v;
    }
}

// ---------------- Kernel 2: MLP v6 — tf32 mma layer 1, fragment-ordered weights ----
#define NB    16
#define XS    260                    // s_x stride (4 mod 32 -> conflict-free frags)
#define H1S   132                    // s_h1 stride
#define MX    (NB * XS)
#define MH1   (NB * H1S)
#define MH2   (NB * 88)
#define SM2_BYTES ((MX + MH1 + MH2) * 4)

__global__ __launch_bounds__(512)
void din_mlp(const float* __restrict__ target, const float* __restrict__ other,
             const float* __restrict__ ob1,
             const float* __restrict__ oW2, const float* __restrict__ ob2,
             const float* __restrict__ oW3, const float* __restrict__ ob3,
             const float* __restrict__ fW,  const float* __restrict__ fb,
             float* __restrict__ out)
{
    extern __shared__ float sm2[];
    float* s_x  = sm2;               // [16][260]
    float* s_h1 = sm2 + MX;          // [16][132]
    float* s_h2 = sm2 + MX + MH1;    // [16][88]

    const int t = threadIdx.x;
    const int B0 = blockIdx.x * NB;

    for (int idx = t; idx < NB * 16; idx += 512) {
        const int bi = idx >> 4, q = idx & 15;
        float4 v = ((const float4*)(g_tmp + (size_t)(B0 + bi) * EE))[q];
        *(float4*)(s_x + bi * XS + 4 * q) = v;
        float4 u = ((const float4*)(target + (size_t)(B0 + bi) * EE))[q];
        *(float4*)(s_x + bi * XS + 64 + 4 * q) = u;
    }
    for (int idx = t; idx < NB * 32; idx += 512) {
        const int bi = idx >> 5, q = idx & 31;
        float4 v = ((const float4*)(other + (size_t)(B0 + bi) * NOTHER))[q];
        *(float4*)(s_x + bi * XS + 128 + 4 * q) = v;
    }
    __syncthreads();

    const int warp = t >> 5, lane = t & 31;
    const int gid = lane >> 2, tig = lane & 3;

    // ---- Layer 1: 256->128 via tf32 mma m16n8k8 ; warp = n-tile, 16 batches ----
    {
        const int nt = warp;                       // n in [8*nt, 8*nt+8)
        float c0 = 0.f, c1 = 0.f, c2 = 0.f, c3 = 0.f;
        const float* xa = s_x + gid * XS + tig;    // rows gid / gid+8
        const uint2* wB = (const uint2*)g_w1t + (nt * 32) * 32 + lane;
        #pragma unroll 4
        for (int ks = 0; ks < 32; ks++) {
            const unsigned a0 = f2tf32(xa[8 * ks]);
            const unsigned a1 = f2tf32(xa[8 * ks + 8 * XS]);
            const unsigned a2 = f2tf32(xa[8 * ks + 4]);
            const unsigned a3 = f2tf32(xa[8 * ks + 4 + 8 * XS]);
            const uint2 bb = wB[ks * 32];
            asm volatile(
                "mma.sync.aligned.m16n8k8.row.col.f32.tf32.tf32.f32 "
                "{%0,%1,%2,%3}, {%4,%5,%6,%7}, {%8,%9}, {%0,%1,%2,%3};"
                : "+f"(c0), "+f"(c1), "+f"(c2), "+f"(c3)
                : "r"(a0), "r"(a1), "r"(a2), "r"(a3), "r"(bb.x), "r"(bb.y));
        }
        const int j0 = nt * 8 + 2 * tig;
        const float b0v = ob1[j0], b1v = ob1[j0 + 1];
        s_h1[gid * H1S + j0]           = fmaxf(c0 + b0v, 0.f);
        s_h1[gid * H1S + j0 + 1]       = fmaxf(c1 + b1v, 0.f);
        s_h1[(gid + 8) * H1S + j0]     = fmaxf(c2 + b0v, 0.f);
        s_h1[(gid + 8) * H1S + j0 + 1] = fmaxf(c3 + b1v, 0.f);
    }
    __syncthreads();

    const float* h10 = s_h1 + warp * H1S;   // warp = batch for layers 2-3

    // ---- Layer 2: 128 -> 85 (fp32, unchanged) ----
    {
        const int j2 = lane + 64;
        const bool g2 = (j2 < F2);
        float a0 = ob2[lane], a1 = ob2[lane + 32], a2 = g2 ? ob2[j2] : 0.f;
        #pragma unroll 4
        for (int k = 0; k < F1; k += 4) {
            const float4 v0 = *(const float4*)(h10 + k);
            #pragma unroll
            for (int i = 0; i < 4; i++) {
                const float* wr = oW2 + (k + i) * F2;
                const float e0 = (i == 0) ? v0.x : (i == 1) ? v0.y : (i == 2) ? v0.z : v0.w;
                a0 = fmaf(e0, wr[lane], a0);
                a1 = fmaf(e0, wr[lane + 32], a1);
                if (g2) a2 = fmaf(e0, wr[j2], a2);
            }
        }
        s_h2[warp * 88 + lane]      = fmaxf(a0, 0.f);
        s_h2[warp * 88 + lane + 32] = fmaxf(a1, 0.f);
        if (g2) s_h2[warp * 88 + j2] = fmaxf(a2, 0.f);
    }
    __syncwarp();

    // ---- Layer 3: 85 -> 64 + final dot (fp32, unchanged) ----
    {
        float a0 = ob3[lane], a1 = ob3[lane + 32];
        const float* h20 = s_h2 + warp * 88;
        #pragma unroll 5
        for (int k = 0; k < F2; k++) {
            const float v0 = h20[k];
            a0 = fmaf(v0, oW3[k * F3 + lane], a0);
            a1 = fmaf(v0, oW3[k * F3 + lane + 32], a1);
        }
        float v = fmaxf(a0, 0.f) * fW[lane] + fmaxf(a1, 0.f) * fW[lane + 32];
        #pragma unroll
        for (int off = 16; off; off >>= 1)
            v += __shfl_xor_sync(0xffffffffu, v, off);
        if (lane == 0)
            out[B0 + warp] = 1.f / (1.f + expf(-(v + fb[0])));
    }
}

extern "C" void kernel_launch(void* const* d_in, const int* in_sizes, int n_in,
                              void* d_out, int out_size)
{
    const float* hist   = (const float*)d_in[0];
    const float* target = (const float*)d_in[1];
    const float* other  = (const float*)d_in[2];
    const float* aW1    = (const float*)d_in[3];
    const float* ab1    = (const float*)d_in[4];
    const float* aW2    = (const float*)d_in[5];
    const float* ab2    = (const float*)d_in[6];
    const float* oW1    = (const float*)d_in[7];
    const float* ob1    = (const float*)d_in[8];
    const float* oW2    = (const float*)d_in[9];
    const float* ob2    = (const float*)d_in[10];
    const float* oW3    = (const float*)d_in[11];
    const float* ob3    = (const float*)d_in[12];
    const float* fW     = (const float*)d_in[13];
    const float* fb     = (const float*)d_in[14];
    float* out = (float*)d_out;

    static int configured = 0;
    if (!configured) {
        cudaFuncSetAttribute(din_attn, cudaFuncAttributeMaxDynamicSharedMemorySize,
                             SM1_BYTES);
        cudaFuncSetAttribute(din_mlp, cudaFuncAttributeMaxDynamicSharedMemorySize,
                             SM2_BYTES);
        configured = 1;
    }
    cvt_w1<<<128, 256>>>(oW1);
    din_attn<<<BB, 256, SM1_BYTES>>>(hist, target, aW1, ab1, aW2, ab2);
    din_mlp<<<BB / NB, 512, SM2_BYTES>>>(target, other, ob1, oW2, ob2,
                                         oW3, ob3, fW, fb, out);
}

// round 16
// speedup vs baseline: 1.1758x; 1.0326x over previous
#include <cuda_runtime.h>
#include <cuda_fp16.h>
#include <math.h>

#define BB     8192
#define MM     200
#define EE     64
#define NOTHER 128
#define H1     96
#define F1     128
#define F2     85
#define F3     64

__device__ float g_tmp[BB * EE];
__device__ unsigned g_w1t[16 * 32 * 32 * 2];   // oW1 tf32 bits, fragment-ordered

__device__ __forceinline__ unsigned f2tf32(float f) {
    unsigned r;
    asm("cvt.rna.tf32.f32 %0, %1;" : "=r"(r) : "f"(f));
    return r;
}

// ---------------- Kernel 0: one-time oW1 -> tf32 fragment layout ----------------
__global__ __launch_bounds__(256)
void cvt_w1(const float* __restrict__ oW1)
{
    const int idx = blockIdx.x * 256 + threadIdx.x;       // 32768 total
    const int r    = idx & 1;
    const int lane = (idx >> 1) & 31;
    const int ks   = (idx >> 6) & 31;
    const int nt   = idx >> 11;
    const int tig = lane & 3, gid = lane >> 2;
    const int k = 8 * ks + tig + 4 * r;
    const int n = 8 * nt + gid;
    g_w1t[idx] = f2tf32(oW1[k * F1 + n]);
}

// ---------------- Kernel 1: attention + weighted sum ----------------
// smem u32: Wf 3072, hist 7488; floats: tgt 64, c0 96, c1 96, w2 96, aij 208, part 512
#define SM1_U32  (3072 + 7488 + 64 + 96 + 96 + 96 + 208 + 512)
#define SM1_BYTES (SM1_U32 * 4)

__global__ __launch_bounds__(256, 4)
void din_attn(const float* __restrict__ hist, const float* __restrict__ target,
              const float* __restrict__ aW1, const float* __restrict__ ab1,
              const float* __restrict__ aW2, const float* __restrict__ ab2)
{
    extern __shared__ unsigned sm1[];
    unsigned* s_Wf = sm1;                 // W1eff half2, fragment-ordered uint2 [ks][nt][lane]
    unsigned* s_h  = sm1 + 3072;          // half2 hist [row*36 + k2], 208 rows
    float* s_tgt  = (float*)(sm1 + 3072 + 7488);
    float* s_c0   = s_tgt + 64;
    float* s_c1   = s_c0 + 96;
    float* s_w2   = s_c1 + 96;
    float* s_aij  = s_w2 + 96;
    float* s_part = s_aij + 208;          // [8][64]

    const int b = blockIdx.x;
    const int t = threadIdx.x;
    const float* hb = hist + (size_t)b * MM * EE;

    if (t < EE) s_tgt[t] = target[(size_t)b * EE + t];
    if (t < H1) s_w2[t]  = aW2[t];
    __syncthreads();

    // ---- stage hist -> smem fp16 ----
    for (int idx = t; idx < MM * 16; idx += 256) {
        const int row = idx >> 4, q = idx & 15;
        float4 v = ((const float4*)(hb + (size_t)row * EE))[q];
        __half2 h01 = __floats2half2_rn(v.x, v.y);
        __half2 h23 = __floats2half2_rn(v.z, v.w);
        uint2 st;
        st.x = *(unsigned*)&h01;
        st.y = *(unsigned*)&h23;
        *(uint2*)(s_h + row * 36 + 2 * q) = st;
    }
    for (int idx = t; idx < 8 * 36; idx += 256)
        s_h[200 * 36 + idx] = 0u;

    // ---- W1eff build, written directly in B-fragment order ----
    for (int idx = t; idx < 32 * H1; idx += 256) {
        const int k2 = idx / H1, n = idx - k2 * H1;
        const int e0 = 2 * k2, e1 = 2 * k2 + 1;
        float v0 = aW1[e0 * H1 + n] + s_tgt[e0] * aW1[(EE + e0) * H1 + n];
        float v1 = aW1[e1 * H1 + n] + s_tgt[e1] * aW1[(EE + e1) * H1 + n];
        __half2 p = __floats2half2_rn(v0, v1);
        const int tigp = k2 & 7, ks = k2 >> 3;
        const int r = tigp >> 2, tg = tigp & 3;
        const int gid = n & 7, nt = n >> 3;
        s_Wf[(((ks * 12 + nt) << 5) + 4 * gid + tg) * 2 + r] = *(unsigned*)&p;
    }

    // ---- c vector: two 32-deep partial sums on disjoint warps ----
    if (t < H1) {                               // e in [0,32)
        float acc = ab1[t];
        #pragma unroll 16
        for (int e = 0; e < 32; e++)
            acc = fmaf(s_tgt[e], aW1[(2 * EE + e) * H1 + t], acc);
        s_c0[t] = acc;
    }
    if (t >= 128 && t < 128 + H1) {             // e in [32,64)
        const int j = t - 128;
        float acc = 0.f;
        #pragma unroll 16
        for (int e = 32; e < 64; e++)
            acc = fmaf(s_tgt[e], aW1[(2 * EE + e) * H1 + j], acc);
        s_c1[j] = acc;
    }
    __syncthreads();

    const int warp = t >> 5, lane = t & 31;
    const int gid = lane >> 2, tig = lane & 3;
    const float bias2 = ab2[0];

    // ---- Phase 1: fp16 mma, two m-tiles interleaved, LDS.64 B-frags ----
    {
        const int mt0 = warp;
        const int mt1 = warp + 8;
        const bool two = (mt1 < 13);

        unsigned A0[4][4], A1[4][4];
        {
            const unsigned* hp0 = s_h + (mt0 * 16 + gid) * 36 + tig;
            #pragma unroll
            for (int ks = 0; ks < 4; ks++) {
                A0[ks][0] = hp0[8 * ks];
                A0[ks][1] = hp0[288 + 8 * ks];
                A0[ks][2] = hp0[8 * ks + 4];
                A0[ks][3] = hp0[288 + 8 * ks + 4];
            }
            if (two) {
                const unsigned* hp1 = s_h + (mt1 * 16 + gid) * 36 + tig;
                #pragma unroll
                for (int ks = 0; ks < 4; ks++) {
                    A1[ks][0] = hp1[8 * ks];
                    A1[ks][1] = hp1[288 + 8 * ks];
                    A1[ks][2] = hp1[8 * ks + 4];
                    A1[ks][3] = hp1[288 + 8 * ks + 4];
                }
            }
        }

        float aij0 = 0.f, aij1 = 0.f, aij2 = 0.f, aij3 = 0.f;
        const uint2* wf = (const uint2*)s_Wf + lane;

        #pragma unroll 1
        for (int nt = 0; nt < 12; nt++) {
            float c0 = 0.f, c1 = 0.f, c2 = 0.f, c3 = 0.f;
            float d0 = 0.f, d1 = 0.f, d2 = 0.f, d3 = 0.f;
            #pragma unroll
            for (int ks = 0; ks < 4; ks++) {
                const uint2 bb = wf[(ks * 12 + nt) << 5];
                asm volatile(
                    "mma.sync.aligned.m16n8k16.row.col.f32.f16.f16.f32 "
                    "{%0,%1,%2,%3}, {%4,%5,%6,%7}, {%8,%9}, {%0,%1,%2,%3};"
                    : "+f"(c0), "+f"(c1), "+f"(c2), "+f"(c3)
                    : "r"(A0[ks][0]), "r"(A0[ks][1]), "r"(A0[ks][2]), "r"(A0[ks][3]),
                      "r"(bb.x), "r"(bb.y));
                if (two)
                    asm volatile(
                        "mma.sync.aligned.m16n8k16.row.col.f32.f16.f16.f32 "
                        "{%0,%1,%2,%3}, {%4,%5,%6,%7}, {%8,%9}, {%0,%1,%2,%3};"
                        : "+f"(d0), "+f"(d1), "+f"(d2), "+f"(d3)
                        : "r"(A1[ks][0]), "r"(A1[ks][1]), "r"(A1[ks][2]), "r"(A1[ks][3]),
                          "r"(bb.x), "r"(bb.y));
            }
            const int j0 = nt * 8 + 2 * tig;
            const float cc0 = s_c0[j0]     + s_c1[j0];
            const float cc1 = s_c0[j0 + 1] + s_c1[j0 + 1];
            const float w0  = s_w2[j0], w1 = s_w2[j0 + 1];
            aij0 = fmaf(fmaxf(c0 + cc0, 0.f), w0, aij0);
            aij0 = fmaf(fmaxf(c1 + cc1, 0.f), w1, aij0);
            aij1 = fmaf(fmaxf(c2 + cc0, 0.f), w0, aij1);
            aij1 = fmaf(fmaxf(c3 + cc1, 0.f), w1, aij1);
            if (two) {
                aij2 = fmaf(fmaxf(d0 + cc0, 0.f), w0, aij2);
                aij2 = fmaf(fmaxf(d1 + cc1, 0.f), w1, aij2);
                aij3 = fmaf(fmaxf(d2 + cc0, 0.f), w0, aij3);
                aij3 = fmaf(fmaxf(d3 + cc1, 0.f), w1, aij3);
            }
        }
        aij0 += __shfl_xor_sync(0xffffffffu, aij0, 1);
        aij0 += __shfl_xor_sync(0xffffffffu, aij0, 2);
        aij1 += __shfl_xor_sync(0xffffffffu, aij1, 1);
        aij1 += __shfl_xor_sync(0xffffffffu, aij1, 2);
        aij2 += __shfl_xor_sync(0xffffffffu, aij2, 1);
        aij2 += __shfl_xor_sync(0xffffffffu, aij2, 2);
        aij3 += __shfl_xor_sync(0xffffffffu, aij3, 1);
        aij3 += __shfl_xor_sync(0xffffffffu, aij3, 2);
        if (tig == 0) {
            const int r0 = mt0 * 16 + gid;
            s_aij[r0] = aij0 + bias2;
            if (r0 + 8 < MM) s_aij[r0 + 8] = aij1 + bias2;
            if (two) {
                const int r2 = mt1 * 16 + gid;
                if (r2 < MM)     s_aij[r2]     = aij2 + bias2;
                if (r2 + 8 < MM) s_aij[r2 + 8] = aij3 + bias2;
            }
        }
    }
    __syncthreads();

    // ---- Phase 2: tmp[e] = sum_m aij[m]*hist[m][e] ----
    {
        const int e2 = lane;
        const int m0 = warp * 25;
        float acc0 = 0.f, acc1 = 0.f;
        #pragma unroll 5
        for (int m = m0; m < m0 + 25; m++) {
            const unsigned u = s_h[m * 36 + e2];
            const __half2 h = *(const __half2*)&u;
            const float2 f = __half22float2(h);
            const float a = s_aij[m];
            acc0 = fmaf(a, f.x, acc0);
            acc1 = fmaf(a, f.y, acc1);
        }
        float2 st; st.x = acc0; st.y = acc1;
        *(float2*)(s_part + warp * 64 + 2 * e2) = st;
    }
    __syncthreads();
    if (t < EE) {
        float v = 0.f;
        #pragma unroll
        for (int c = 0; c < 8; c++)
            v += s_part[c * 64 + t];
        g_tmp[(size_t)b * EE + t] = v;
    }
}

// ---------------- Kernel 2: MLP v6 (R15, unchanged) ----------------
#define NB    16
#define XS    260
#define H1S   132
#define MX    (NB * XS)
#define MH1   (NB * H1S)
#define MH2   (NB * 88)
#define SM2_BYTES ((MX + MH1 + MH2) * 4)

__global__ __launch_bounds__(512)
void din_mlp(const float* __restrict__ target, const float* __restrict__ other,
             const float* __restrict__ ob1,
             const float* __restrict__ oW2, const float* __restrict__ ob2,
             const float* __restrict__ oW3, const float* __restrict__ ob3,
             const float* __restrict__ fW,  const float* __restrict__ fb,
             float* __restrict__ out)
{
    extern __shared__ float sm2[];
    float* s_x  = sm2;
    float* s_h1 = sm2 + MX;
    float* s_h2 = sm2 + MX + MH1;

    const int t = threadIdx.x;
    const int B0 = blockIdx.x * NB;

    for (int idx = t; idx < NB * 16; idx += 512) {
        const int bi = idx >> 4, q = idx & 15;
        float4 v = ((const float4*)(g_tmp + (size_t)(B0 + bi) * EE))[q];
        *(float4*)(s_x + bi * XS + 4 * q) = v;
        float4 u = ((const float4*)(target + (size_t)(B0 + bi) * EE))[q];
        *(float4*)(s_x + bi * XS + 64 + 4 * q) = u;
    }
    for (int idx = t; idx < NB * 32; idx += 512) {
        const int bi = idx >> 5, q = idx & 31;
        float4 v = ((const float4*)(other + (size_t)(B0 + bi) * NOTHER))[q];
        *(float4*)(s_x + bi * XS + 128 + 4 * q) = v;
    }
    __syncthreads();

    const int warp = t >> 5, lane = t & 31;
    const int gid = lane >> 2, tig = lane & 3;

    {
        const int nt = warp;
        float c0 = 0.f, c1 = 0.f, c2 = 0.f, c3 = 0.f;
        const float* xa = s_x + gid * XS + tig;
        const uint2* wB = (const uint2*)g_w1t + (nt * 32) * 32 + lane;
        #pragma unroll 4
        for (int ks = 0; ks < 32; ks++) {
            const unsigned a0 = f2tf32(xa[8 * ks]);
            const unsigned a1 = f2tf32(xa[8 * ks + 8 * XS]);
            const unsigned a2 = f2tf32(xa[8 * ks + 4]);
            const unsigned a3 = f2tf32(xa[8 * ks + 4 + 8 * XS]);
            const uint2 bb = wB[ks * 32];
            asm volatile(
                "mma.sync.aligned.m16n8k8.row.col.f32.tf32.tf32.f32 "
                "{%0,%1,%2,%3}, {%4,%5,%6,%7}, {%8,%9}, {%0,%1,%2,%3};"
                : "+f"(c0), "+f"(c1), "+f"(c2), "+f"(c3)
                : "r"(a0), "r"(a1), "r"(a2), "r"(a3), "r"(bb.x), "r"(bb.y));
        }
        const int j0 = nt * 8 + 2 * tig;
        const float b0v = ob1[j0], b1v = ob1[j0 + 1];
        s_h1[gid * H1S + j0]           = fmaxf(c0 + b0v, 0.f);
        s_h1[gid * H1S + j0 + 1]       = fmaxf(c1 + b1v, 0.f);
        s_h1[(gid + 8) * H1S + j0]     = fmaxf(c2 + b0v, 0.f);
        s_h1[(gid + 8) * H1S + j0 + 1] = fmaxf(c3 + b1v, 0.f);
    }
    __syncthreads();

    const float* h10 = s_h1 + warp * H1S;

    {
        const int j2 = lane + 64;
        const bool g2 = (j2 < F2);
        float a0 = ob2[lane], a1 = ob2[lane + 32], a2 = g2 ? ob2[j2] : 0.f;
        #pragma unroll 4
        for (int k = 0; k < F1; k += 4) {
            const float4 v0 = *(const float4*)(h10 + k);
            #pragma unroll
            for (int i = 0; i < 4; i++) {
                const float* wr = oW2 + (k + i) * F2;
                const float e0 = (i == 0) ? v0.x : (i == 1) ? v0.y : (i == 2) ? v0.z : v0.w;
                a0 = fmaf(e0, wr[lane], a0);
                a1 = fmaf(e0, wr[lane + 32], a1);
                if (g2) a2 = fmaf(e0, wr[j2], a2);
            }
        }
        s_h2[warp * 88 + lane]      = fmaxf(a0, 0.f);
        s_h2[warp * 88 + lane + 32] = fmaxf(a1, 0.f);
        if (g2) s_h2[warp * 88 + j2] = fmaxf(a2, 0.f);
    }
    __syncwarp();

    {
        float a0 = ob3[lane], a1 = ob3[lane + 32];
        const float* h20 = s_h2 + warp * 88;
        #pragma unroll 5
        for (int k = 0; k < F2; k++) {
            const float v0 = h20[k];
            a0 = fmaf(v0, oW3[k * F3 + lane], a0);
            a1 = fmaf(v0, oW3[k * F3 + lane + 32], a1);
        }
        float v = fmaxf(a0, 0.f) * fW[lane] + fmaxf(a1, 0.f) * fW[lane + 32];
        #pragma unroll
        for (int off = 16; off; off >>= 1)
            v += __shfl_xor_sync(0xffffffffu, v, off);
        if (lane == 0)
            out[B0 + warp] = 1.f / (1.f + expf(-(v + fb[0])));
    }
}

extern "C" void kernel_launch(void* const* d_in, const int* in_sizes, int n_in,
                              void* d_out, int out_size)
{
    const float* hist   = (const float*)d_in[0];
    const float* target = (const float*)d_in[1];
    const float* other  = (const float*)d_in[2];
    const float* aW1    = (const float*)d_in[3];
    const float* ab1    = (const float*)d_in[4];
    const float* aW2    = (const float*)d_in[5];
    const float* ab2    = (const float*)d_in[6];
    const float* oW1    = (const float*)d_in[7];
    const float* ob1    = (const float*)d_in[8];
    const float* oW2    = (const float*)d_in[9];
    const float* ob2    = (const float*)d_in[10];
    const float* oW3    = (const float*)d_in[11];
    const float* ob3    = (const float*)d_in[12];
    const float* fW     = (const float*)d_in[13];
    const float* fb     = (const float*)d_in[14];
    float* out = (float*)d_out;

    static int configured = 0;
    if (!configured) {
        cudaFuncSetAttribute(din_attn, cudaFuncAttributeMaxDynamicSharedMemorySize,
                             SM1_BYTES);
        cudaFuncSetAttribute(din_mlp, cudaFuncAttributeMaxDynamicSharedMemorySize,
                             SM2_BYTES);
        configured = 1;
    }
    cvt_w1<<<128, 256>>>(oW1);
    din_attn<<<BB, 256, SM1_BYTES>>>(hist, target, aW1, ab1, aW2, ab2);
    din_mlp<<<BB / NB, 512, SM2_BYTES>>>(target, other, ob1, oW2, ob2,
                                         oW3, ob3, fW, fb, out);
}

// round 17
// speedup vs baseline: 1.2242x; 1.0412x over previous
#include <cuda_runtime.h>
#include <cuda_fp16.h>
#include <math.h>

#define BB     8192
#define MM     200
#define EE     64
#define NOTHER 128
#define H1     96
#define F1     128
#define F2     85
#define F3     64

__device__ float g_tmp[BB * EE];

__device__ __forceinline__ unsigned f2tf32(float f) {
    unsigned r;
    asm("cvt.rna.tf32.f32 %0, %1;" : "=r"(r) : "f"(f));
    return r;
}

// ---------------- Kernel 1: attention + weighted sum (5 CTAs/SM) ----------------
// smem u32: Wf 3072, hist 200*36=7200; floats: tgt 64, c0 96, c1 96, w2 96, aij 208, part 512
// total 11344 u32 = 45376 B ; +1KB runtime reserve = 46400 ; x5 = 232000 <= 233472 OK
#define SM1_U32  (3072 + 7200 + 64 + 96 + 96 + 96 + 208 + 512)
#define SM1_BYTES (SM1_U32 * 4)

__global__ __launch_bounds__(256, 5)
void din_attn(const float* __restrict__ hist, const float* __restrict__ target,
              const float* __restrict__ aW1, const float* __restrict__ ab1,
              const float* __restrict__ aW2, const float* __restrict__ ab2)
{
    extern __shared__ unsigned sm1[];
    unsigned* s_Wf = sm1;                 // W1eff half2, fragment-ordered uint2 [ks][nt][lane]
    unsigned* s_h  = sm1 + 3072;          // half2 hist [row*36 + k2], 200 rows
    float* s_tgt  = (float*)(sm1 + 3072 + 7200);
    float* s_c0   = s_tgt + 64;
    float* s_c1   = s_c0 + 96;
    float* s_w2   = s_c1 + 96;
    float* s_aij  = s_w2 + 96;
    float* s_part = s_aij + 208;          // [8][64]

    const int b = blockIdx.x;
    const int t = threadIdx.x;
    const float* hb = hist + (size_t)b * MM * EE;

    if (t < EE) s_tgt[t] = target[(size_t)b * EE + t];
    if (t < H1) s_w2[t]  = aW2[t];
    __syncthreads();

    // ---- stage hist -> smem fp16 (200 rows, no pad; OOR tile-12 reads stay
    //      in-bounds smem garbage and their outputs are discarded by r<200 guards) ----
    for (int idx = t; idx < MM * 16; idx += 256) {
        const int row = idx >> 4, q = idx & 15;
        float4 v = ((const float4*)(hb + (size_t)row * EE))[q];
        __half2 h01 = __floats2half2_rn(v.x, v.y);
        __half2 h23 = __floats2half2_rn(v.z, v.w);
        uint2 st;
        st.x = *(unsigned*)&h01;
        st.y = *(unsigned*)&h23;
        *(uint2*)(s_h + row * 36 + 2 * q) = st;
    }

    // ---- W1eff build, written directly in B-fragment order ----
    for (int idx = t; idx < 32 * H1; idx += 256) {
        const int k2 = idx / H1, n = idx - k2 * H1;
        const int e0 = 2 * k2, e1 = 2 * k2 + 1;
        float v0 = aW1[e0 * H1 + n] + s_tgt[e0] * aW1[(EE + e0) * H1 + n];
        float v1 = aW1[e1 * H1 + n] + s_tgt[e1] * aW1[(EE + e1) * H1 + n];
        __half2 p = __floats2half2_rn(v0, v1);
        const int tigp = k2 & 7, ks = k2 >> 3;
        const int r = tigp >> 2, tg = tigp & 3;
        const int gid = n & 7, nt = n >> 3;
        s_Wf[(((ks * 12 + nt) << 5) + 4 * gid + tg) * 2 + r] = *(unsigned*)&p;
    }

    // ---- c vector: two 32-deep partial sums on disjoint warps ----
    if (t < H1) {
        float acc = ab1[t];
        #pragma unroll 16
        for (int e = 0; e < 32; e++)
            acc = fmaf(s_tgt[e], aW1[(2 * EE + e) * H1 + t], acc);
        s_c0[t] = acc;
    }
    if (t >= 128 && t < 128 + H1) {
        const int j = t - 128;
        float acc = 0.f;
        #pragma unroll 16
        for (int e = 32; e < 64; e++)
            acc = fmaf(s_tgt[e], aW1[(2 * EE + e) * H1 + j], acc);
        s_c1[j] = acc;
    }
    __syncthreads();

    const int warp = t >> 5, lane = t & 31;
    const int gid = lane >> 2, tig = lane & 3;
    const float bias2 = ab2[0];

    // ---- Phase 1: fp16 mma m16n8k16, single m-tile round-robin, LDS.64 B-frags ----
    for (int mt = warp; mt < 13; mt += 8) {
        unsigned A[4][4];
        const unsigned* hp = s_h + (mt * 16 + gid) * 36 + tig;
        #pragma unroll
        for (int ks = 0; ks < 4; ks++) {
            A[ks][0] = hp[8 * ks];
            A[ks][1] = hp[288 + 8 * ks];
            A[ks][2] = hp[8 * ks + 4];
            A[ks][3] = hp[288 + 8 * ks + 4];
        }

        float aij0 = 0.f, aij1 = 0.f;
        const uint2* wf = (const uint2*)s_Wf + lane;

        #pragma unroll 1
        for (int nt = 0; nt < 12; nt++) {
            float c0 = 0.f, c1 = 0.f, c2 = 0.f, c3 = 0.f;
            #pragma unroll
            for (int ks = 0; ks < 4; ks++) {
                const uint2 bb = wf[(ks * 12 + nt) << 5];
                asm volatile(
                    "mma.sync.aligned.m16n8k16.row.col.f32.f16.f16.f32 "
                    "{%0,%1,%2,%3}, {%4,%5,%6,%7}, {%8,%9}, {%0,%1,%2,%3};"
                    : "+f"(c0), "+f"(c1), "+f"(c2), "+f"(c3)
                    : "r"(A[ks][0]), "r"(A[ks][1]), "r"(A[ks][2]), "r"(A[ks][3]),
                      "r"(bb.x), "r"(bb.y));
            }
            const int j0 = nt * 8 + 2 * tig;
            const float cc0 = s_c0[j0]     + s_c1[j0];
            const float cc1 = s_c0[j0 + 1] + s_c1[j0 + 1];
            const float w0  = s_w2[j0], w1 = s_w2[j0 + 1];
            aij0 = fmaf(fmaxf(c0 + cc0, 0.f), w0, aij0);
            aij0 = fmaf(fmaxf(c1 + cc1, 0.f), w1, aij0);
            aij1 = fmaf(fmaxf(c2 + cc0, 0.f), w0, aij1);
            aij1 = fmaf(fmaxf(c3 + cc1, 0.f), w1, aij1);
        }
        aij0 += __shfl_xor_sync(0xffffffffu, aij0, 1);
        aij0 += __shfl_xor_sync(0xffffffffu, aij0, 2);
        aij1 += __shfl_xor_sync(0xffffffffu, aij1, 1);
        aij1 += __shfl_xor_sync(0xffffffffu, aij1, 2);
        if (tig == 0) {
            const int r0 = mt * 16 + gid;
            if (r0 < MM)     s_aij[r0]     = aij0 + bias2;
            if (r0 + 8 < MM) s_aij[r0 + 8] = aij1 + bias2;
        }
    }
    __syncthreads();

    // ---- Phase 2: tmp[e] = sum_m aij[m]*hist[m][e] ----
    {
        const int e2 = lane;
        const int m0 = warp * 25;
        float acc0 = 0.f, acc1 = 0.f;
        #pragma unroll 5
        for (int m = m0; m < m0 + 25; m++) {
            const unsigned u = s_h[m * 36 + e2];
            const __half2 h = *(const __half2*)&u;
            const float2 f = __half22float2(h);
            const float a = s_aij[m];
            acc0 = fmaf(a, f.x, acc0);
            acc1 = fmaf(a, f.y, acc1);
        }
        float2 st; st.x = acc0; st.y = acc1;
        *(float2*)(s_part + warp * 64 + 2 * e2) = st;
    }
    __syncthreads();
    if (t < EE) {
        float v = 0.f;
        #pragma unroll
        for (int c = 0; c < 8; c++)
            v += s_part[c * 64 + t];
        g_tmp[(size_t)b * EE + t] = v;
    }
}

// ---------------- Kernel 2: MLP — tf32 mma layer 1, inline B-frag cvt from oW1 ----
#define NB    16
#define XS    260
#define H1S   132
#define MX    (NB * XS)
#define MH1   (NB * H1S)
#define MH2   (NB * 88)
#define SM2_BYTES ((MX + MH1 + MH2) * 4)

__global__ __launch_bounds__(512)
void din_mlp(const float* __restrict__ target, const float* __restrict__ other,
             const float* __restrict__ oW1, const float* __restrict__ ob1,
             const float* __restrict__ oW2, const float* __restrict__ ob2,
             const float* __restrict__ oW3, const float* __restrict__ ob3,
             const float* __restrict__ fW,  const float* __restrict__ fb,
             float* __restrict__ out)
{
    extern __shared__ float sm2[];
    float* s_x  = sm2;
    float* s_h1 = sm2 + MX;
    float* s_h2 = sm2 + MX + MH1;

    const int t = threadIdx.x;
    const int B0 = blockIdx.x * NB;

    for (int idx = t; idx < NB * 16; idx += 512) {
        const int bi = idx >> 4, q = idx & 15;
        float4 v = ((const float4*)(g_tmp + (size_t)(B0 + bi) * EE))[q];
        *(float4*)(s_x + bi * XS + 4 * q) = v;
        float4 u = ((const float4*)(target + (size_t)(B0 + bi) * EE))[q];
        *(float4*)(s_x + bi * XS + 64 + 4 * q) = u;
    }
    for (int idx = t; idx < NB * 32; idx += 512) {
        const int bi = idx >> 5, q = idx & 31;
        float4 v = ((const float4*)(other + (size_t)(B0 + bi) * NOTHER))[q];
        *(float4*)(s_x + bi * XS + 128 + 4 * q) = v;
    }
    __syncthreads();

    const int warp = t >> 5, lane = t & 31;
    const int gid = lane >> 2, tig = lane & 3;

    // ---- Layer 1: 256->128 via tf32 mma m16n8k8 ; B-frags converted inline (L1-hot) ----
    {
        const int nt = warp;
        float c0 = 0.f, c1 = 0.f, c2 = 0.f, c3 = 0.f;
        const float* xa = s_x + gid * XS + tig;
        const float* wbase = oW1 + tig * F1 + 8 * nt + gid;   // + ks*1024 ; +512 for k+4
        #pragma unroll 4
        for (int ks = 0; ks < 32; ks++) {
            const unsigned a0 = f2tf32(xa[8 * ks]);
            const unsigned a1 = f2tf32(xa[8 * ks + 8 * XS]);
            const unsigned a2 = f2tf32(xa[8 * ks + 4]);
            const unsigned a3 = f2tf32(xa[8 * ks + 4 + 8 * XS]);
            const unsigned bx = f2tf32(wbase[ks * 1024]);
            const unsigned by = f2tf32(wbase[ks * 1024 + 512]);
            asm volatile(
                "mma.sync.aligned.m16n8k8.row.col.f32.tf32.tf32.f32 "
                "{%0,%1,%2,%3}, {%4,%5,%6,%7}, {%8,%9}, {%0,%1,%2,%3};"
                : "+f"(c0), "+f"(c1), "+f"(c2), "+f"(c3)
                : "r"(a0), "r"(a1), "r"(a2), "r"(a3), "r"(bx), "r"(by));
        }
        const int j0 = nt * 8 + 2 * tig;
        const float b0v = ob1[j0], b1v = ob1[j0 + 1];
        s_h1[gid * H1S + j0]           = fmaxf(c0 + b0v, 0.f);
        s_h1[gid * H1S + j0 + 1]       = fmaxf(c1 + b1v, 0.f);
        s_h1[(gid + 8) * H1S + j0]     = fmaxf(c2 + b0v, 0.f);
        s_h1[(gid + 8) * H1S + j0 + 1] = fmaxf(c3 + b1v, 0.f);
    }
    __syncthreads();

    const float* h10 = s_h1 + warp * H1S;

    // ---- Layer 2: 128 -> 85 ----
    {
        const int j2 = lane + 64;
        const bool g2 = (j2 < F2);
        float a0 = ob2[lane], a1 = ob2[lane + 32], a2 = g2 ? ob2[j2] : 0.f;
        #pragma unroll 4
        for (int k = 0; k < F1; k += 4) {
            const float4 v0 = *(const float4*)(h10 + k);
            #pragma unroll
            for (int i = 0; i < 4; i++) {
                const float* wr = oW2 + (k + i) * F2;
                const float e0 = (i == 0) ? v0.x : (i == 1) ? v0.y : (i == 2) ? v0.z : v0.w;
                a0 = fmaf(e0, wr[lane], a0);
                a1 = fmaf(e0, wr[lane + 32], a1);
                if (g2) a2 = fmaf(e0, wr[j2], a2);
            }
        }
        s_h2[warp * 88 + lane]      = fmaxf(a0, 0.f);
        s_h2[warp * 88 + lane + 32] = fmaxf(a1, 0.f);
        if (g2) s_h2[warp * 88 + j2] = fmaxf(a2, 0.f);
    }
    __syncwarp();

    // ---- Layer 3: 85 -> 64 + final dot ----
    {
        float a0 = ob3[lane], a1 = ob3[lane + 32];
        const float* h20 = s_h2 + warp * 88;
        #pragma unroll 5
        for (int k = 0; k < F2; k++) {
            const float v0 = h20[k];
            a0 = fmaf(v0, oW3[k * F3 + lane], a0);
            a1 = fmaf(v0, oW3[k * F3 + lane + 32], a1);
        }
        float v = fmaxf(a0, 0.f) * fW[lane] + fmaxf(a1, 0.f) * fW[lane + 32];
        #pragma unroll
        for (int off = 16; off; off >>= 1)
            v += __shfl_xor_sync(0xffffffffu, v, off);
        if (lane == 0)
            out[B0 + warp] = 1.f / (1.f + expf(-(v + fb[0])));
    }
}

extern "C" void kernel_launch(void* const* d_in, const int* in_sizes, int n_in,
                              void* d_out, int out_size)
{
    const float* hist   = (const float*)d_in[0];
    const float* target = (const float*)d_in[1];
    const float* other  = (const float*)d_in[2];
    const float* aW1    = (const float*)d_in[3];
    const float* ab1    = (const float*)d_in[4];
    const float* aW2    = (const float*)d_in[5];
    const float* ab2    = (const float*)d_in[6];
    const float* oW1    = (const float*)d_in[7];
    const float* ob1    = (const float*)d_in[8];
    const float* oW2    = (const float*)d_in[9];
    const float* ob2    = (const float*)d_in[10];
    const float* oW3    = (const float*)d_in[11];
    const float* ob3    = (const float*)d_in[12];
    const float* fW     = (const float*)d_in[13];
    const float* fb     = (const float*)d_in[14];
    float* out = (float*)d_out;

    static int configured = 0;
    if (!configured) {
        cudaFuncSetAttribute(din_attn, cudaFuncAttributeMaxDynamicSharedMemorySize,
                             SM1_BYTES);
        cudaFuncSetAttribute(din_mlp, cudaFuncAttributeMaxDynamicSharedMemorySize,
                             SM2_BYTES);
        configured = 1;
    }
    din_attn<<<BB, 256, SM1_BYTES>>>(hist, target, aW1, ab1, aW2, ab2);
    din_mlp<<<BB / NB, 512, SM2_BYTES>>>(target, other, oW1, ob1, oW2, ob2,
                                         oW3, ob3, fW, fb, out);
}